// round 2
// baseline (speedup 1.0000x reference)
#include <cuda_runtime.h>

#define D    2048
#define E    16
#define R    16
#define QO   2048
#define VO   512
#define NTOK 4096
#define SCALE 2.0f
#define TM   32
#define MAXTILES 144

typedef unsigned long long u64;

__device__ __forceinline__ u64 pk2(float lo, float hi) {
    u64 r; asm("mov.b64 %0,{%1,%2};" : "=l"(r) : "f"(lo), "f"(hi)); return r;
}
__device__ __forceinline__ u64 fma2(u64 a, u64 b, u64 c) {
    u64 d; asm("fma.rn.f32x2 %0,%1,%2,%3;" : "=l"(d) : "l"(a), "l"(b), "l"(c)); return d;
}
__device__ __forceinline__ float2 upk(u64 v) {
    float2 f; asm("mov.b64 {%0,%1},%2;" : "=f"(f.x), "=f"(f.y) : "l"(v)); return f;
}

// ---------------- scratch ----------------
__device__ int   g_top_idx[NTOK * 2];
__device__ float g_top_w[NTOK * 2];
__device__ int   g_off[2][E + 1];
__device__ int   g_tileoff[2][E + 1];
__device__ int   g_perm[2][NTOK];
__device__ float g_lowq[2][NTOK][R];
__device__ float g_lowv[2][NTOK][R];

// ---------------- router: logits, softmax, top-2, renorm ----------------
__global__ void __launch_bounds__(256) k_router(const float* __restrict__ h,
                                                const float* __restrict__ W) {
    int t = blockIdx.x;
    int warp = threadIdx.x >> 5, lane = threadIdx.x & 31;
    const float4* h4 = (const float4*)(h + (size_t)t * D);
    int e0 = warp * 2;
    const float4* wa = (const float4*)(W + (size_t)e0 * D);
    const float4* wb = (const float4*)(W + (size_t)(e0 + 1) * D);
    float s0 = 0.f, s1 = 0.f;
    #pragma unroll 4
    for (int i = lane; i < D / 4; i += 32) {
        float4 hv = h4[i], a = wa[i], b = wb[i];
        s0 += hv.x * a.x + hv.y * a.y + hv.z * a.z + hv.w * a.w;
        s1 += hv.x * b.x + hv.y * b.y + hv.z * b.z + hv.w * b.w;
    }
    #pragma unroll
    for (int o = 16; o > 0; o >>= 1) {
        s0 += __shfl_xor_sync(0xffffffffu, s0, o);
        s1 += __shfl_xor_sync(0xffffffffu, s1, o);
    }
    __shared__ float lg[E];
    if (lane == 0) { lg[e0] = s0; lg[e0 + 1] = s1; }
    __syncthreads();
    if (threadIdx.x == 0) {
        float m = lg[0];
        #pragma unroll
        for (int i = 1; i < E; i++) m = fmaxf(m, lg[i]);
        float ex[E], Z = 0.f;
        #pragma unroll
        for (int i = 0; i < E; i++) { ex[i] = expf(lg[i] - m); Z += ex[i]; }
        int i0 = 0;
        #pragma unroll
        for (int i = 1; i < E; i++) if (lg[i] > lg[i0]) i0 = i;
        int i1 = (i0 == 0) ? 1 : 0;
        #pragma unroll
        for (int i = 0; i < E; i++) if (i != i0 && lg[i] > lg[i1]) i1 = i;
        float p0 = ex[i0] / Z, p1 = ex[i1] / Z;
        float dn = p0 + p1 + 1e-20f;
        g_top_idx[t * 2]     = i0;
        g_top_idx[t * 2 + 1] = i1;
        g_top_w[t * 2]       = SCALE * p0 / dn;
        g_top_w[t * 2 + 1]   = SCALE * p1 / dn;
    }
}

// ---------------- fused count + scan + scatter (single block) ----------------
__global__ void __launch_bounds__(1024) k_route_aux(int n) {
    __shared__ int cnt[2 * E];
    __shared__ int fill[2 * E];
    int tid = threadIdx.x, lane = tid & 31;
    if (tid < 2 * E) cnt[tid] = 0;
    __syncthreads();

    // histogram (warp-aggregated)
    for (int idx = tid; idx < 2 * n; idx += 1024) {
        int key = (idx & 1) * E + g_top_idx[idx];
        unsigned mask = __match_any_sync(__activemask(), key);
        int leader = __ffs(mask) - 1;
        if (lane == leader) atomicAdd(&cnt[key], __popc(mask));
    }
    __syncthreads();

    // scan
    if (tid == 0) {
        #pragma unroll
        for (int k = 0; k < 2; k++) {
            int acc = 0, tacc = 0;
            for (int e = 0; e < E; e++) {
                g_off[k][e] = acc; fill[k * E + e] = acc; g_tileoff[k][e] = tacc;
                int c = cnt[k * E + e];
                acc += c; tacc += (c + TM - 1) / TM;
            }
            g_off[k][E] = acc; g_tileoff[k][E] = tacc;
        }
    }
    __syncthreads();

    // scatter
    for (int idx = tid; idx < 2 * n; idx += 1024) {
        int k = idx & 1, t = idx >> 1;
        int key = k * E + g_top_idx[idx];
        unsigned mask = __match_any_sync(__activemask(), key);
        int leader = __ffs(mask) - 1;
        int base = 0;
        if (lane == leader) base = atomicAdd(&fill[key], __popc(mask));
        base = __shfl_sync(mask, base, leader);
        int rank = __popc(mask & ((1u << lane) - 1u));
        g_perm[k][base + rank] = t;
    }
}

// ---------------- low projection (f32x2, dd-pair packed) ----------------
// grid (MAXTILES, 2), 128 threads. Tile: 32 tokens x 32 outs (16 q | 16 v).
// Per thread: 2 tokens x 4 cols. A staged TRANSPOSED [col][dd] for LDS.64.
#define HSP 68
#define ATP 70
__global__ void __launch_bounds__(128) k_low(const float* __restrict__ h,
                                             const float* __restrict__ qa,
                                             const float* __restrict__ va) {
    int k = blockIdx.y;
    int tileId = blockIdx.x;
    if (tileId >= g_tileoff[k][E]) return;
    int e = 0;
    #pragma unroll
    for (int i = 1; i < E; i++) if (tileId >= g_tileoff[k][i]) e = i;
    int tb = tileId - g_tileoff[k][e];
    int base = g_off[k][e] + tb * TM;
    int nrows = min(TM, g_off[k][e + 1] - base);

    __shared__ float sH[TM * HSP];
    __shared__ float sA[32 * ATP];
    __shared__ int   toks[TM];

    int tid = threadIdx.x;
    if (tid < TM) toks[tid] = g_perm[k][base + ((tid < nrows) ? tid : 0)];
    __syncthreads();

    int trow = tid >> 3;         // 0..15 -> tokens trow*2, trow*2+1
    int tcol = tid & 7;          // 0..7  -> cols tcol*4 .. +3
    int c0 = tcol * 4;

    u64 acc[2][4];
    #pragma unroll
    for (int i = 0; i < 2; i++)
        #pragma unroll
        for (int j = 0; j < 4; j++) acc[i][j] = 0ull;

    const float* Aq = qa + (size_t)e * D * R;
    const float* Av = va + (size_t)e * D * R;

    for (int kc = 0; kc < D; kc += 64) {
        // stage A transposed: 64 dd x 32 cols
        #pragma unroll
        for (int i = 0; i < 4; i++) {
            int f = tid + 128 * i;          // 0..511
            int dd = f >> 3, part = f & 7;  // part 0..3 q quads, 4..7 v quads
            const float* src = (part < 4)
                ? Aq + (size_t)(kc + dd) * R + (part & 3) * 4
                : Av + (size_t)(kc + dd) * R + (part & 3) * 4;
            float4 v = *(const float4*)src;
            int col = part * 4;             // 0..28
            sA[(col + 0) * ATP + dd] = v.x;
            sA[(col + 1) * ATP + dd] = v.y;
            sA[(col + 2) * ATP + dd] = v.z;
            sA[(col + 3) * ATP + dd] = v.w;
        }
        // stage h: 32 tokens x 64 floats
        #pragma unroll
        for (int i = 0; i < 4; i++) {
            int idx = tid + 128 * i;        // 0..511
            int row = idx >> 4, q4 = idx & 15;
            float4 hv = *(const float4*)(h + (size_t)toks[row] * D + kc + q4 * 4);
            *(float4*)&sH[row * HSP + q4 * 4] = hv;
        }
        __syncthreads();

        int t0 = trow * 2, t1 = t0 + 1;
        #pragma unroll 8
        for (int dd = 0; dd < 64; dd += 2) {
            u64 h0 = *(const u64*)&sH[t0 * HSP + dd];
            u64 h1 = *(const u64*)&sH[t1 * HSP + dd];
            u64 a0 = *(const u64*)&sA[(c0 + 0) * ATP + dd];
            u64 a1 = *(const u64*)&sA[(c0 + 1) * ATP + dd];
            u64 a2 = *(const u64*)&sA[(c0 + 2) * ATP + dd];
            u64 a3 = *(const u64*)&sA[(c0 + 3) * ATP + dd];
            acc[0][0] = fma2(h0, a0, acc[0][0]);
            acc[0][1] = fma2(h0, a1, acc[0][1]);
            acc[0][2] = fma2(h0, a2, acc[0][2]);
            acc[0][3] = fma2(h0, a3, acc[0][3]);
            acc[1][0] = fma2(h1, a0, acc[1][0]);
            acc[1][1] = fma2(h1, a1, acc[1][1]);
            acc[1][2] = fma2(h1, a2, acc[1][2]);
            acc[1][3] = fma2(h1, a3, acc[1][3]);
        }
        __syncthreads();
    }

    #pragma unroll
    for (int i = 0; i < 2; i++) {
        int row = trow * 2 + i;
        if (row < nrows) {
            int t = toks[row];
            float w = g_top_w[t * 2 + k];
            float4 o;
            float2 v0 = upk(acc[i][0]), v1 = upk(acc[i][1]);
            float2 v2 = upk(acc[i][2]), v3 = upk(acc[i][3]);
            o.x = (v0.x + v0.y) * w;
            o.y = (v1.x + v1.y) * w;
            o.z = (v2.x + v2.y) * w;
            o.w = (v3.x + v3.y) * w;
            int pos = base + row;
            if (c0 < 16) *(float4*)&g_lowq[k][pos][c0]      = o;
            else         *(float4*)&g_lowv[k][pos][c0 - 16] = o;
        }
    }
}

// ---------------- delta (f32x2, token-pair packed) ----------------
// grid (MAXTILES, 20), 256 threads. Tile: 32 tokens x 128 cols.
// Per thread: 4 tokens (2 f32x2 pairs) x 4 cols.
#define BSP 132
#define LTP 34
__global__ void __launch_bounds__(256) k_delta(int k,
                                               const float* __restrict__ qb,
                                               const float* __restrict__ vb,
                                               float* __restrict__ out) {
    int tileId = blockIdx.x;
    if (tileId >= g_tileoff[k][E]) return;
    int e = 0;
    #pragma unroll
    for (int i = 1; i < E; i++) if (tileId >= g_tileoff[k][i]) e = i;
    int tb = tileId - g_tileoff[k][e];
    int base = g_off[k][e] + tb * TM;
    int nrows = min(TM, g_off[k][e + 1] - base);

    int cc = blockIdx.y;
    const float* B; float* O; int ldO, ldB;
    const float (*low)[R];
    if (cc < 16) {
        int colBase = cc * 128;
        B = qb + (size_t)e * R * QO + colBase;
        O = out + colBase; ldO = QO; ldB = QO;
        low = g_lowq[k];
    } else {
        int colBase = (cc - 16) * 128;
        B = vb + (size_t)e * R * VO + colBase;
        O = out + (size_t)NTOK * QO + colBase; ldO = VO; ldB = VO;
        low = g_lowv[k];
    }

    __shared__ float sB[R * BSP];     // [r][128 cols]
    __shared__ float sL[R * LTP];     // transposed: [r][32 toks]
    __shared__ int   toks[TM];

    int tid = threadIdx.x;
    #pragma unroll
    for (int i = 0; i < 2; i++) {
        int idx = tid + 256 * i;      // 0..511 -> 16 r x 32 quads
        int r = idx >> 5, q4 = idx & 31;
        *(float4*)&sB[r * BSP + q4 * 4] = *(const float4*)(B + (size_t)r * ldB + q4 * 4);
    }
    #pragma unroll
    for (int i = 0; i < 2; i++) {
        int idx = tid + 256 * i;      // 0..511 -> 32 rows x 16 r
        int row = idx >> 4, r = idx & 15;
        sL[r * LTP + row] = low[base + ((row < nrows) ? row : 0)][r];
    }
    if (tid < TM) toks[tid] = (tid < nrows) ? g_perm[k][base + tid] : 0;
    __syncthreads();

    int trow = tid >> 5;              // warp id 0..7 -> tokens trow*4..+3
    int tcol = tid & 31;              // cols tcol*4..+3
    int tbase = trow * 4;

    u64 acc[2][4];
    #pragma unroll
    for (int p = 0; p < 2; p++)
        #pragma unroll
        for (int j = 0; j < 4; j++) acc[p][j] = 0ull;

    #pragma unroll
    for (int r = 0; r < R; r++) {
        float4 b4 = *(const float4*)&sB[r * BSP + tcol * 4];
        u64 b0 = pk2(b4.x, b4.x), b1 = pk2(b4.y, b4.y);
        u64 b2 = pk2(b4.z, b4.z), b3 = pk2(b4.w, b4.w);
        u64 l0 = *(const u64*)&sL[r * LTP + tbase];       // toks tbase, tbase+1
        u64 l1 = *(const u64*)&sL[r * LTP + tbase + 2];   // toks tbase+2, tbase+3
        acc[0][0] = fma2(l0, b0, acc[0][0]);
        acc[0][1] = fma2(l0, b1, acc[0][1]);
        acc[0][2] = fma2(l0, b2, acc[0][2]);
        acc[0][3] = fma2(l0, b3, acc[0][3]);
        acc[1][0] = fma2(l1, b0, acc[1][0]);
        acc[1][1] = fma2(l1, b1, acc[1][1]);
        acc[1][2] = fma2(l1, b2, acc[1][2]);
        acc[1][3] = fma2(l1, b3, acc[1][3]);
    }

    #pragma unroll
    for (int p = 0; p < 2; p++) {
        float2 u0 = upk(acc[p][0]), u1 = upk(acc[p][1]);
        float2 u2 = upk(acc[p][2]), u3 = upk(acc[p][3]);
        #pragma unroll
        for (int half = 0; half < 2; half++) {
            int row = tbase + 2 * p + half;
            if (row < nrows) {
                float4 v = half == 0 ? make_float4(u0.x, u1.x, u2.x, u3.x)
                                     : make_float4(u0.y, u1.y, u2.y, u3.y);
                float* pt = O + (size_t)toks[row] * ldO + tcol * 4;
                if (k == 1) {
                    float4 old = *(const float4*)pt;
                    v.x += old.x; v.y += old.y; v.z += old.z; v.w += old.w;
                }
                *(float4*)pt = v;
            }
        }
    }
}

// ---------------- launcher ----------------
extern "C" void kernel_launch(void* const* d_in, const int* in_sizes, int n_in,
                              void* d_out, int out_size) {
    const float* h  = (const float*)d_in[0];
    const float* W  = (const float*)d_in[1];
    const float* qa = (const float*)d_in[2];
    const float* qb = (const float*)d_in[3];
    const float* va = (const float*)d_in[4];
    const float* vb = (const float*)d_in[5];
    float* out = (float*)d_out;
    int n = in_sizes[0] / D;   // 4096

    k_router<<<n, 256>>>(h, W);
    k_route_aux<<<1, 1024>>>(n);
    dim3 gb(MAXTILES, 2);
    k_low<<<gb, 128>>>(h, qa, va);
    dim3 gc(MAXTILES, 20);
    k_delta<<<gc, 256>>>(0, qb, vb, out);
    k_delta<<<gc, 256>>>(1, qb, vb, out);
}